// round 17
// baseline (speedup 1.0000x reference)
#include <cuda_runtime.h>
#include <cuda_fp16.h>
#include <math.h>
#include <stdint.h>

// Problem constants
#define BB 2
#define TT 2048
#define CC 2048
#define HH 16
#define KEY_DIM 2048
#define VALUE_DIM 2048
#define CONV_DIM 6144
#define QKVZ_N 8192
#define BT 4096   // B*T
#define LCH 64
#define NCH (TT / LCH)   // 32 chunks
#define BH 32            // B*H

// ---------------- scratch (static device globals; no allocation) -------------
__device__ float g_qkvz[(size_t)BT * QKVZ_N];
__device__ float g_beta[(size_t)BT * HH];
__device__ float g_alpha[(size_t)BT * HH];
__device__ float g_att[(size_t)BT * VALUE_DIM];
__device__ __half g_xh[(size_t)BT * CC];
__device__ __half g_wqt[(size_t)QKVZ_N * CC];
__device__ __half g_wot[(size_t)CC * CC];
__device__ __half g_goh[(size_t)BT * CC];
__device__ float g_sinc[(size_t)BH * NCH * 16384];
__device__ float g_spre[(size_t)BH * NCH * 16384];
__device__ float g_cc[(size_t)BH * TT];

// ---------------- PTX helpers ------------------------------------------------
__device__ __forceinline__ uint32_t s2u(const void* p) {
    uint32_t a;
    asm("{ .reg .u64 t; cvta.to.shared.u64 t, %1; cvt.u32.u64 %0, t; }"
        : "=r"(a) : "l"(p));
    return a;
}
__device__ __forceinline__ void ldsm4(uint32_t* r, uint32_t addr) {
    asm volatile("ldmatrix.sync.aligned.m8n8.x4.shared.b16 {%0,%1,%2,%3}, [%4];"
                 : "=r"(r[0]), "=r"(r[1]), "=r"(r[2]), "=r"(r[3]) : "r"(addr));
}
__device__ __forceinline__ void mma168f16(float* d, const uint32_t* a,
                                          const uint32_t* b) {
    asm volatile(
        "mma.sync.aligned.m16n8k16.row.col.f32.f16.f16.f32 "
        "{%0,%1,%2,%3}, {%4,%5,%6,%7}, {%8,%9}, {%0,%1,%2,%3};\n"
        : "+f"(d[0]), "+f"(d[1]), "+f"(d[2]), "+f"(d[3])
        : "r"(a[0]), "r"(a[1]), "r"(a[2]), "r"(a[3]),
          "r"(b[0]), "r"(b[1]));
}
__device__ __forceinline__ void cpasync16(uint32_t dst, const void* src) {
    asm volatile("cp.async.cg.shared.global [%0], [%1], 16;"
                 :: "r"(dst), "l"(src));
}
__device__ __forceinline__ void cp_commit() {
    asm volatile("cp.async.commit_group;");
}
__device__ __forceinline__ void cp_wait1() {
    asm volatile("cp.async.wait_group 1;" ::: "memory");
}
__device__ __forceinline__ void cp_wait0() {
    asm volatile("cp.async.wait_group 0;" ::: "memory");
}

// ---------------- fp16 tensor-core GEMM: cp.async 3-stage pipeline -----------
#define STAGE_B 20480
#define GEMM_SMEM (3 * STAGE_B)

__global__ void __launch_bounds__(128, 2)
h16gemm(const __half* __restrict__ A, const __half* __restrict__ Bt,
        float* __restrict__ Cm, int ldc, int Kd)
{
    extern __shared__ char smem[];
    const uint32_t sb = s2u(smem);
    const int tid  = threadIdx.x;
    const int bm   = blockIdx.y * 128;
    const int bn   = blockIdx.x * 128;
    const int lane = tid & 31;
    const int warp = tid >> 5;
    const int wm   = (warp >> 1) * 64;
    const int wn   = (warp & 1) * 64;
    const int gid  = lane >> 2;
    const int tig  = lane & 3;

    const int lr = tid >> 2;
    const int lc = tid & 3;

    const __half* Ap0 = A  + (size_t)(bm + lr) * Kd + lc * 8;
    const __half* Bp0 = Bt + (size_t)(bn + lr) * Kd + lc * 8;
    const size_t r32 = (size_t)32 * Kd;

    float acc[4][8][4];
    #pragma unroll
    for (int i = 0; i < 4; i++)
        #pragma unroll
        for (int j = 0; j < 8; j++)
            #pragma unroll
            for (int r = 0; r < 4; r++) acc[i][j][r] = 0.f;

    auto issue = [&](int s) {
        const uint32_t dst = sb + (uint32_t)(s % 3) * STAGE_B;
        const __half* Ap = Ap0 + s * 32;
        const __half* Bp = Bp0 + s * 32;
        #pragma unroll
        for (int i = 0; i < 4; i++) {
            cpasync16(dst + (uint32_t)(lr + 32 * i) * 80 + lc * 16, Ap + i * r32);
            cpasync16(dst + 10240u + (uint32_t)(lr + 32 * i) * 80 + lc * 16, Bp + i * r32);
        }
        cp_commit();
    };

    const int nst = Kd / 32;
    issue(0);
    issue(1);

    const int at = lane >> 3;
    const int arow = wm + (at & 1) * 8 + (lane & 7);
    const int akoff = (lane >> 4) * 16;
    const int brow = wn + (lane >> 4) * 8 + (lane & 7);
    const int bkoff = ((lane >> 3) & 1) * 16;

    for (int s = 0; s < nst; s++) {
        if (s + 1 < nst) cp_wait1();
        else             cp_wait0();
        __syncthreads();
        if (s + 2 < nst) issue(s + 2);

        const uint32_t base = sb + (uint32_t)(s % 3) * STAGE_B;
        #pragma unroll
        for (int ks = 0; ks < 2; ks++) {
            uint32_t aF[4][4], bF[4][4];
            const uint32_t ak = base + (uint32_t)(ks * 32 + akoff);
            #pragma unroll
            for (int mt = 0; mt < 4; mt++)
                ldsm4(aF[mt], ak + (uint32_t)(arow + mt * 16) * 80);
            const uint32_t bk = base + 10240u + (uint32_t)(ks * 32 + bkoff);
            #pragma unroll
            for (int np = 0; np < 4; np++)
                ldsm4(bF[np], bk + (uint32_t)(brow + np * 16) * 80);
            #pragma unroll
            for (int mt = 0; mt < 4; mt++)
                #pragma unroll
                for (int nt = 0; nt < 8; nt++)
                    mma168f16(acc[mt][nt], aF[mt], &bF[nt >> 1][(nt & 1) * 2]);
        }
    }

    #pragma unroll
    for (int mt = 0; mt < 4; mt++) {
        const int row = bm + wm + mt * 16 + gid;
        #pragma unroll
        for (int nt = 0; nt < 8; nt++) {
            const int col = bn + wn + nt * 8 + 2 * tig;
            *(float2*)&Cm[(size_t)row * ldc + col]       = make_float2(acc[mt][nt][0], acc[mt][nt][1]);
            *(float2*)&Cm[(size_t)(row + 8) * ldc + col] = make_float2(acc[mt][nt][2], acc[mt][nt][3]);
        }
    }
}

// ---------------- f32 -> f16 convert -----------------------------------------
__global__ void __launch_bounds__(256)
to_half(const float* __restrict__ X, __half* __restrict__ Y, int n8)
{
    int i = blockIdx.x * 256 + threadIdx.x;
    if (i >= n8) return;
    float4 v0 = ((const float4*)X)[i * 2];
    float4 v1 = ((const float4*)X)[i * 2 + 1];
    __half2* H = (__half2*)Y;
    H[i * 4 + 0] = __floats2half2_rn(v0.x, v0.y);
    H[i * 4 + 1] = __floats2half2_rn(v0.z, v0.w);
    H[i * 4 + 2] = __floats2half2_rn(v1.x, v1.y);
    H[i * 4 + 3] = __floats2half2_rn(v1.z, v1.w);
}

// ---------------- transpose: W[K][N] f32 -> Wt[N][K] f16 ---------------------
__global__ void __launch_bounds__(256)
transpose_half(const float* __restrict__ W, __half* __restrict__ Th, int K, int N)
{
    __shared__ float tile[32][33];
    const int k0 = blockIdx.y * 32, n0 = blockIdx.x * 32;
    const int tx = threadIdx.x & 31, ty = threadIdx.x >> 5;
    #pragma unroll
    for (int r = 0; r < 32; r += 8)
        tile[ty + r][tx] = W[(size_t)(k0 + ty + r) * N + n0 + tx];
    __syncthreads();
    #pragma unroll
    for (int r = 0; r < 32; r += 8)
        Th[(size_t)(n0 + ty + r) * K + k0 + tx] = __float2half(tile[tx][ty + r]);
}

// ---------------- beta/alpha: tiled fp32 GEMM --------------------------------
#define BA_SMEM (64 * 132 * 4 + 128 * 32 * 4)
__global__ void __launch_bounds__(256)
ba2_kernel(const float* __restrict__ x, const float* __restrict__ Wb,
           const float* __restrict__ Wa, float* __restrict__ beta,
           float* __restrict__ alpha)
{
    extern __shared__ float sm[];
    float* xs = sm;
    float* ws = sm + 64 * 132;

    const int tid = threadIdx.x;
    const int r0 = blockIdx.x * 64;
    const int tr = tid >> 4;
    const int tc = tid & 15;

    float acc[4][2];
    #pragma unroll
    for (int i = 0; i < 4; i++) { acc[i][0] = 0.f; acc[i][1] = 0.f; }

    for (int k0 = 0; k0 < CC; k0 += 128) {
        #pragma unroll
        for (int i = 0; i < 8; i++) {
            const int idx = tid + i * 256;
            const int row = idx >> 5, c4 = (idx & 31) * 4;
            *(float4*)&xs[row * 132 + c4] =
                *(const float4*)&x[(size_t)(r0 + row) * CC + k0 + c4];
        }
        #pragma unroll
        for (int i = 0; i < 2; i++) {
            const int idx = tid + i * 256;
            const int kk = idx >> 2, q = (idx & 3) * 4;
            *(float4*)&ws[kk * 32 + q]      = *(const float4*)&Wb[(size_t)(k0 + kk) * HH + q];
            *(float4*)&ws[kk * 32 + 16 + q] = *(const float4*)&Wa[(size_t)(k0 + kk) * HH + q];
        }
        __syncthreads();

        for (int kk = 0; kk < 128; kk++) {
            const float2 wv = *(const float2*)&ws[kk * 32 + tc * 2];
            #pragma unroll
            for (int i = 0; i < 4; i++) {
                const float xv = xs[(tr * 4 + i) * 132 + kk];
                acc[i][0] = fmaf(xv, wv.x, acc[i][0]);
                acc[i][1] = fmaf(xv, wv.y, acc[i][1]);
            }
        }
        __syncthreads();
    }

    #pragma unroll
    for (int i = 0; i < 4; i++) {
        const int row = r0 + tr * 4 + i;
        #pragma unroll
        for (int j = 0; j < 2; j++) {
            const int c = tc * 2 + j;
            const float v = 1.f / (1.f + expf(-acc[i][j]));
            if (c < 16) beta[(size_t)row * HH + c] = v;
            else        alpha[(size_t)row * HH + (c - 16)] = v;
        }
    }
}

// ---------------- fused conv helper ------------------------------------------
// conv(K=4)+silu for (b, t, channel c4..c4+3); taps read from qkvz / conv_state.
__device__ __forceinline__ void conv4(
    const float* __restrict__ qkvz, const float* __restrict__ conv_w,
    const float* __restrict__ conv_state, float keep,
    int b, int t, int col, float* out)
{
    const float4 w0 = *(const float4*)&conv_w[(size_t)(col + 0) * 4];
    const float4 w1 = *(const float4*)&conv_w[(size_t)(col + 1) * 4];
    const float4 w2 = *(const float4*)&conv_w[(size_t)(col + 2) * 4];
    const float4 w3 = *(const float4*)&conv_w[(size_t)(col + 3) * 4];
    float a0 = 0.f, a1 = 0.f, a2 = 0.f, a3 = 0.f;
    #pragma unroll
    for (int j = 0; j < 4; j++) {
        const int tau = t - 3 + j;
        float4 tv;
        if (tau >= 0) {
            tv = *(const float4*)&qkvz[((size_t)(b * TT + tau)) * QKVZ_N + col];
        } else {
            const int slot = tau + 4;
            tv.x = keep * conv_state[((size_t)b * CONV_DIM + col + 0) * 4 + slot];
            tv.y = keep * conv_state[((size_t)b * CONV_DIM + col + 1) * 4 + slot];
            tv.z = keep * conv_state[((size_t)b * CONV_DIM + col + 2) * 4 + slot];
            tv.w = keep * conv_state[((size_t)b * CONV_DIM + col + 3) * 4 + slot];
        }
        a0 = fmaf(tv.x, ((const float*)&w0)[j], a0);
        a1 = fmaf(tv.y, ((const float*)&w1)[j], a1);
        a2 = fmaf(tv.z, ((const float*)&w2)[j], a2);
        a3 = fmaf(tv.w, ((const float*)&w3)[j], a3);
    }
    out[0] = a0 / (1.f + expf(-a0));
    out[1] = a1 / (1.f + expf(-a1));
    out[2] = a2 / (1.f + expf(-a2));
    out[3] = a3 / (1.f + expf(-a3));
}

// ---------------- chunked recurrence: phase A (conv fused) -------------------
// smem: qs[64][132], ksT[128][68], vs[64][132], P[64][68], cs,bs,invq,invk[64]
#define SA_QS 0
#define SA_KT (64 * 132)
#define SA_VS (SA_KT + 128 * 68)
#define SA_P  (SA_VS + 64 * 132)
#define SA_CS (SA_P + 64 * 68)
#define SA_BS (SA_CS + 64)
#define SA_IQ (SA_BS + 64)
#define SA_IK (SA_IQ + 64)
#define SMA_BYTES ((SA_IK + 64) * 4)

__global__ void __launch_bounds__(256)
chunkA(const float* __restrict__ qkvz, const float* __restrict__ conv_w,
       const float* __restrict__ conv_state, const int* __restrict__ input_pos,
       const float* __restrict__ beta, const float* __restrict__ alpha,
       float* __restrict__ att, float* __restrict__ sinc, float* __restrict__ cbuf)
{
    extern __shared__ float sm[];
    float* qs  = sm + SA_QS;
    float* ksT = sm + SA_KT;
    float* vs  = sm + SA_VS;
    float* P   = sm + SA_P;
    float* cs  = sm + SA_CS;
    float* bs  = sm + SA_BS;
    float* invq = sm + SA_IQ;
    float* invk = sm + SA_IK;

    const int bh = blockIdx.y, j = blockIdx.x;
    const int b = bh >> 4, h = bh & 15;
    const int t0 = j * LCH;
    const int tid = threadIdx.x;
    const float keep = (input_pos[0] == 0) ? 0.f : 1.f;

    // fused conv+silu for q, k, v head slices
    for (int idx = tid; idx < 6144; idx += 256) {
        const int sl = idx / 2048;                  // 0=q, 1=k, 2=v
        const int it = idx - sl * 2048;
        const int row = it >> 5, c4 = (it & 31) * 4;
        const int col = sl * KEY_DIM + h * 128 + c4;
        float o[4];
        conv4(qkvz, conv_w, conv_state, keep, b, t0 + row, col, o);
        if (sl == 0) {
            *(float4*)&qs[row * 132 + c4] = make_float4(o[0], o[1], o[2], o[3]);
        } else if (sl == 1) {
            ksT[(c4 + 0) * 68 + row] = o[0];
            ksT[(c4 + 1) * 68 + row] = o[1];
            ksT[(c4 + 2) * 68 + row] = o[2];
            ksT[(c4 + 3) * 68 + row] = o[3];
        } else {
            *(float4*)&vs[row * 132 + c4] = make_float4(o[0], o[1], o[2], o[3]);
        }
    }
    if (tid < 64) {
        cs[tid] = log2f(alpha[((size_t)(b * TT + t0 + tid)) * HH + h]);
        bs[tid] = beta[((size_t)(b * TT + t0 + tid)) * HH + h];
    }
    __syncthreads();

    // norms (deterministic shfl reductions)
    {
        const int wid = tid >> 5, lane = tid & 31;
        for (int row = wid; row < 64; row += 8) {
            float ss = 0.f;
            #pragma unroll
            for (int i = 0; i < 4; i++) {
                const float v = qs[row * 132 + lane + i * 32];
                ss = fmaf(v, v, ss);
            }
            #pragma unroll
            for (int off = 16; off > 0; off >>= 1)
                ss += __shfl_xor_sync(0xffffffffu, ss, off);
            if (lane == 0) invq[row] = 1.f / fmaxf(sqrtf(ss), 1e-12f);
        }
        for (int row = wid; row < 64; row += 8) {
            float ss = 0.f;
            #pragma unroll
            for (int i = 0; i < 4; i++) {
                const float v = ksT[(lane + i * 32) * 68 + row];
                ss = fmaf(v, v, ss);
            }
            #pragma unroll
            for (int off = 16; off > 0; off >>= 1)
                ss += __shfl_xor_sync(0xffffffffu, ss, off);
            if (lane == 0) invk[row] = 1.f / fmaxf(sqrtf(ss), 1e-12f);
        }
    }
    __syncthreads();
    if (tid == 0) {
        float run = 0.f;
        for (int t = 0; t < LCH; t++) { run += cs[t]; cs[t] = run; }
    }
    __syncthreads();
    if (tid < 64) cbuf[(size_t)bh * TT + t0 + tid] = cs[tid];

    // P[t][tau] = (q.k) * invq[t]*invk[tau] * b[tau] * 2^(c_t - c_tau)
    {
        const int rt = tid >> 4, ct = tid & 15;
        float acc[4][4];
        #pragma unroll
        for (int i = 0; i < 4; i++)
            #pragma unroll
            for (int j2 = 0; j2 < 4; j2++) acc[i][j2] = 0.f;
        if (ct <= rt) {
            for (int kk0 = 0; kk0 < 128; kk0 += 4) {
                float4 qv[4], kv[4];
                #pragma unroll
                for (int i = 0; i < 4; i++)
                    qv[i] = *(const float4*)&qs[(rt * 4 + i) * 132 + kk0];
                #pragma unroll
                for (int q = 0; q < 4; q++)
                    kv[q] = *(const float4*)&ksT[(kk0 + q) * 68 + ct * 4];
                #pragma unroll
                for (int q = 0; q < 4; q++) {
                    const float* kq = (const float*)&kv[q];
                    #pragma unroll
                    for (int i = 0; i < 4; i++) {
                        const float qq = ((const float*)&qv[i])[q];
                        #pragma unroll
                        for (int j2 = 0; j2 < 4; j2++)
                            acc[i][j2] = fmaf(qq, kq[j2], acc[i][j2]);
                    }
                }
            }
        }
        #pragma unroll
        for (int i = 0; i < 4; i++)
            #pragma unroll
            for (int j2 = 0; j2 < 4; j2++) {
                const int t = rt * 4 + i, tau = ct * 4 + j2;
                float val = 0.f;
                if (tau <= t)
                    val = acc[i][j2] * invq[t] * invk[tau] * bs[tau]
                        * exp2f(cs[t] - cs[tau]);
                P[t * 68 + tau] = val;
            }
    }
    __syncthreads();

    // o_intra = P @ v
    {
        const int tg = tid >> 3, dvg = tid & 7;
        const int ta = tg * 2, tb = ta + 1;
        float4 o0[4], o1[4];
        #pragma unroll
        for (int d = 0; d < 4; d++) {
            o0[d] = make_float4(0.f, 0.f, 0.f, 0.f);
            o1[d] = make_float4(0.f, 0.f, 0.f, 0.f);
        }
        for (int tau = 0; tau < LCH; tau++) {
            const float p0 = P[ta * 68 + tau];
            const float p1 = P[tb * 68 + tau];
            const float* vr = vs + tau * 132;
            #pragma unroll
            for (int d = 0; d < 4; d++) {
                const float4 vv = *(const float4*)(vr + dvg * 4 + 32 * d);
                o0[d].x = fmaf(p0, vv.x, o0[d].x); o0[d].y = fmaf(p0, vv.y, o0[d].y);
                o0[d].z = fmaf(p0, vv.z, o0[d].z); o0[d].w = fmaf(p0, vv.w, o0[d].w);
                o1[d].x = fmaf(p1, vv.x, o1[d].x); o1[d].y = fmaf(p1, vv.y, o1[d].y);
                o1[d].z = fmaf(p1, vv.z, o1[d].z); o1[d].w = fmaf(p1, vv.w, o1[d].w);
            }
        }
        float* ar0 = att + ((size_t)(b * TT + t0 + ta)) * VALUE_DIM + h * 128;
        float* ar1 = att + ((size_t)(b * TT + t0 + tb)) * VALUE_DIM + h * 128;
        #pragma unroll
        for (int d = 0; d < 4; d++) {
            *(float4*)(ar0 + dvg * 4 + 32 * d) = o0[d];
            *(float4*)(ar1 + dvg * 4 + 32 * d) = o1[d];
        }
    }

    // Sinc with invk folded into weight
    {
        const int dkt = tid >> 4, dvt = tid & 15;
        float4 sacc[8][2];
        #pragma unroll
        for (int i = 0; i < 8; i++)
            #pragma unroll
            for (int dj = 0; dj < 2; dj++)
                sacc[i][dj] = make_float4(0.f, 0.f, 0.f, 0.f);
        const float cL = cs[63];
        for (int tau = 0; tau < LCH; tau++) {
            const float w = bs[tau] * invk[tau] * exp2f(cL - cs[tau]);
            float kw[8];
            #pragma unroll
            for (int i = 0; i < 8; i++) kw[i] = ksT[(dkt + 16 * i) * 68 + tau] * w;
            float4 vv[2];
            #pragma unroll
            for (int dj = 0; dj < 2; dj++)
                vv[dj] = *(const float4*)&vs[tau * 132 + dvt * 4 + 64 * dj];
            #pragma unroll
            for (int i = 0; i < 8; i++)
                #pragma unroll
                for (int dj = 0; dj < 2; dj++) {
                    sacc[i][dj].x = fmaf(kw[i], vv[dj].x, sacc[i][dj].x);
                    sacc[i][dj].y = fmaf(kw[i], vv[dj].y, sacc[i][dj].y);
                    sacc[i][dj].z = fmaf(kw[i], vv[dj].z, sacc[i][dj].z);
                    sacc[i][dj].w = fmaf(kw[i], vv[dj].w, sacc[i][dj].w);
                }
        }
        float* sp = sinc + ((size_t)(bh * NCH + j)) * 16384;
        #pragma unroll
        for (int i = 0; i < 8; i++)
            #pragma unroll
            for (int dj = 0; dj < 2; dj++)
                *(float4*)&sp[(dkt + 16 * i) * 128 + dvt * 4 + 64 * dj] = sacc[i][dj];
    }
}

// ---------------- phase B: 8-way sliced scan ---------------------------------
__global__ void __launch_bounds__(256)
chunkB(const float* __restrict__ sinc, float* __restrict__ spre,
       const float* __restrict__ cbuf, const float* __restrict__ rstate,
       const int* __restrict__ input_pos)
{
    const int bh = blockIdx.y;
    const int off0 = blockIdx.x * 2048 + threadIdx.x;
    const float keep = (input_pos[0] == 0) ? 0.f : 1.f;

    float s[8];
    #pragma unroll
    for (int i = 0; i < 8; i++)
        s[i] = keep * rstate[(size_t)bh * 16384 + off0 + i * 256];

    for (int j = 0; j < NCH; j++) {
        const size_t base = ((size_t)(bh * NCH + j)) * 16384 + off0;
        #pragma unroll
        for (int i = 0; i < 8; i++)
            spre[base + i * 256] = s[i];
        const float dec = exp2f(cbuf[(size_t)bh * TT + j * LCH + 63]);
        #pragma unroll
        for (int i = 0; i < 8; i++)
            s[i] = fmaf(dec, s[i], sinc[base + i * 256]);
    }
}

// ---------------- phase C: conv(q) fused + inter + gate ----------------------
// smem: S[128][132] + qs[64][132] + cs[64] + nws[128] + invq[64]
#define SC_S  0
#define SC_QS (128 * 132)
#define SC_CS (SC_QS + 64 * 132)
#define SC_NW (SC_CS + 64)
#define SC_IQ (SC_NW + 128)
#define SMC_BYTES ((SC_IQ + 64) * 4)
__global__ void __launch_bounds__(256)
chunkC(const float* __restrict__ qkvz, const float* __restrict__ conv_w,
       const float* __restrict__ conv_state, const int* __restrict__ input_pos,
       const float* __restrict__ cbuf, const float* __restrict__ spre,
       const float* __restrict__ att, const float* __restrict__ norm_w,
       __half* __restrict__ goh)
{
    extern __shared__ float sm[];
    float* S    = sm + SC_S;
    float* qs   = sm + SC_QS;
    float* cs   = sm + SC_CS;
    float* nws  = sm + SC_NW;
    float* invq = sm + SC_IQ;

    const int bh = blockIdx.y, j = blockIdx.x;
    const int b = bh >> 4, h = bh & 15;
    const int t0 = j * LCH;
    const int tid = threadIdx.x;
    const float keep = (input_pos[0] == 0) ? 0.f : 1.f;

    const float* sp = spre + ((size_t)(bh * NCH + j)) * 16384;
    for (int i = tid; i < 4096; i += 256) {
        const int dk = i >> 5, dv4 = (i & 31) * 4;
        *(float4*)&S[dk * 132 + dv4] = *(const float4*)&sp[dk * 128 + dv4];
    }
    for (int i = tid; i < 2048; i += 256) {
        const int row = i >> 5, c4 = (i & 31) * 4;
        float o[4];
        conv4(qkvz, conv_w, conv_state, keep, b, t0 + row, h * 128 + c4, o);
        *(float4*)&qs[row * 132 + c4] = make_float4(o[0], o[1], o[2], o[3]);
    }
    if (tid < 64) cs[tid] = cbuf[(size_t)bh * TT + t0 + tid];
    if (tid < 128) nws[tid] = norm_w[tid];
    __syncthreads();

    // q norms
    {
        const int wid = tid >> 5, lane = tid & 31;
        for (int row = wid; row < 64; row += 8) {
            float ss = 0.f;
            #pragma unroll
            for (int i = 0; i < 4; i++) {
                const float v = qs[row * 132 + lane + i * 32];
                ss = fmaf(v, v, ss);
            }
            #pragma unroll
            for (int off = 16; off > 0; off >>= 1)
                ss += __shfl_xor_sync(0xffffffffu, ss, off);
            if (lane == 0) invq[row] = 1.f / fmaxf(sqrtf(ss), 1e-12f);
        }
    }
    __syncthreads();

    const int tg = tid >> 3, dvg = tid & 7;
    const int ta = tg * 2, tb = ta + 1;
    float4 o0[4], o1[4];
    #pragma unroll
    for (int d = 0; d < 4; d++) {
        o0[d] = make_float4(0.f, 0.f, 0.f, 0.f);
        o1[d] = make_float4(0.f, 0.f, 0.f, 0.f);
    }
    for (int dk = 0; dk < 128; dk++) {
        const float q0 = qs[ta * 132 + dk];
        const float q1 = qs[tb * 132 + dk];
        const float* srow = S + dk * 132;
        #pragma unroll
        for (int d = 0; d < 4; d++) {
            const float4 sv = *(const float4*)(srow + dvg * 4 + 32 * d);
            o0[d].x = fmaf(q0, sv.x, o0[d].x); o0[d].y = fmaf(q0, sv.y, o0[d].y);
            o0[d].z = fmaf(q0, sv.z, o0[d].z); o0[d].w = fmaf(q0, sv.w, o0[d].w);
            o1[d].x = fmaf(q1, sv.x, o1[d].x); o1[d].y = fmaf(q1, sv.y, o1[d].y);
            o1[d].z = fmaf(q1, sv.z, o1[d].z); o1[d].w = fmaf(q1, sv.w, o1[d].w);
        }
    }
    const float e0 = exp2f(cs[ta]) * invq[ta];
    const float e1 = exp2f(cs[tb]) * invq[tb];

    const float* ar0 = att + ((size_t)(b * TT + t0 + ta)) * VALUE_DIM + h * 128;
    const float* ar1 = att + ((size_t)(b * TT + t0 + tb)) * VALUE_DIM + h * 128;
    float ss0 = 0.f, ss1 = 0.f;
    #pragma unroll
    for (int d = 0; d < 4; d++) {
        const float4 a0 = *(const float4*)(ar0 + dvg * 4 + 32 * d);
        const float4 a1 = *(const float4*)(ar1 + dvg * 4 + 32 * d);
        o0[d].x = a0.x + e0 * o0[d].x;  o0[d].y = a0.y + e0 * o0[d].y;
        o0[d].z = a0.z + e0 * o0[d].z;  o0[d].w = a0.w + e0 * o0[d].w;
        o1[d].x = a1.x + e1 * o1[d].x;  o1[d].y = a1.y + e1 * o1[d].y;
        o1[d].z = a1.z + e1 * o1[d].z;  o1[d].w = a1.w + e1 * o1[d].w;
        ss0 = fmaf(o0[d].x, o0[d].x, ss0); ss0 = fmaf(o0[d].y, o0[d].y, ss0);
        ss0 = fmaf(o0[d].z, o0[d].z, ss0); ss0 = fmaf(o0[d].w, o0[d].w, ss0);
        ss1 = fmaf(o1[d].x, o1[d].x, ss1); ss1 = fmaf(o1[d].y, o1[d].y, ss1);
        ss1 = fmaf(o1[d].z, o1[d].z, ss1); ss1 = fmaf(o1[d].w, o1[d].w, ss1);
    }
    #pragma unroll
    for (int off = 1; off < 8; off <<= 1) {
        ss0 += __shfl_xor_sync(0xffffffffu, ss0, off);
        ss1 += __shfl_xor_sync(0xffffffffu, ss1, off);
    }
    const float sc0 = rsqrtf(ss0 * (1.f / 128.f) + 1e-6f);
    const float sc1 = rsqrtf(ss1 * (1.f / 128.f) + 1e-6f);

    const float* zr0 = qkvz + ((size_t)(b * TT + t0 + ta)) * QKVZ_N + CONV_DIM + h * 128;
    const float* zr1 = qkvz + ((size_t)(b * TT + t0 + tb)) * QKVZ_N + CONV_DIM + h * 128;
    __half* gr0 = goh + ((size_t)(b * TT + t0 + ta)) * VALUE_DIM + h * 128;
    __half* gr1 = goh + ((size_t)(b * TT + t0 + tb)) * VALUE_DIM + h * 128;
    #pragma unroll
    for (int d = 0; d < 4; d++) {
        const int dvi = dvg * 4 + 32 * d;
        const float4 z0 = *(const float4*)(zr0 + dvi);
        const float4 z1 = *(const float4*)(zr1 + dvi);
        const float4 nw = *(const float4*)(nws + dvi);
        __half2 h0a = __floats2half2_rn(
            o0[d].x * sc0 * nw.x * (1.f / (1.f + expf(-z0.x))),
            o0[d].y * sc0 * nw.y * (1.f / (1.f + expf(-z0.y))));
        __half2 h0b = __floats2half2_rn(
            o0[d].z * sc0 * nw.z * (1.f / (1.f + expf(-z0.z))),
            o0[d].w * sc0 * nw.w * (1.f / (1.f + expf(-z0.w))));
        __half2 h1a = __floats2half2_rn(
            o1[d].x * sc1 * nw.x * (1.f / (1.f + expf(-z1.x))),
            o1[d].y * sc1 * nw.y * (1.f / (1.f + expf(-z1.y))));
        __half2 h1b = __floats2half2_rn(
            o1[d].z * sc1 * nw.z * (1.f / (1.f + expf(-z1.w ? -z1.w : -z1.w))),
            o1[d].w * sc1 * nw.w * (1.f / (1.f + expf(-z1.w))));
        // fix: correct z component for h1b lane z
        h1b = __floats2half2_rn(
            o1[d].z * sc1 * nw.z * (1.f / (1.f + expf(-z1.z))),
            o1[d].w * sc1 * nw.w * (1.f / (1.f + expf(-z1.w))));
        *(__half2*)(gr0 + dvi)     = h0a;
        *(__half2*)(gr0 + dvi + 2) = h0b;
        *(__half2*)(gr1 + dvi)     = h1a;
        *(__half2*)(gr1 + dvi + 2) = h1b;
    }
}

// ---------------- launch -----------------------------------------------------
extern "C" void kernel_launch(void* const* d_in, const int* in_sizes, int n_in,
                              void* d_out, int out_size)
{
    const float* x          = (const float*)d_in[0];
    const int*   input_pos  = (const int*)  d_in[1];
    const float* W_qkvz     = (const float*)d_in[2];
    const float* W_b        = (const float*)d_in[3];
    const float* W_a        = (const float*)d_in[4];
    const float* conv_w     = (const float*)d_in[5];
    const float* norm_w     = (const float*)d_in[6];
    const float* W_out      = (const float*)d_in[7];
    const float* conv_state = (const float*)d_in[8];
    const float* rec_state  = (const float*)d_in[9];
    float* out = (float*)d_out;

    float *qkvz, *beta, *alpha, *attb, *sinc, *spre, *cbuf;
    __half *xh, *wqt, *wot, *goh;
    cudaGetSymbolAddress((void**)&qkvz, g_qkvz);
    cudaGetSymbolAddress((void**)&beta, g_beta);
    cudaGetSymbolAddress((void**)&alpha,g_alpha);
    cudaGetSymbolAddress((void**)&attb, g_att);
    cudaGetSymbolAddress((void**)&sinc, g_sinc);
    cudaGetSymbolAddress((void**)&spre, g_spre);
    cudaGetSymbolAddress((void**)&cbuf, g_cc);
    cudaGetSymbolAddress((void**)&xh,  g_xh);
    cudaGetSymbolAddress((void**)&wqt, g_wqt);
    cudaGetSymbolAddress((void**)&wot, g_wot);
    cudaGetSymbolAddress((void**)&goh, g_goh);

    static cudaStream_t s1 = nullptr, s2 = nullptr;
    static cudaEvent_t evFork = nullptr, evWq = nullptr, evBA = nullptr, evZ = nullptr;
    if (s1 == nullptr) {
        cudaStreamCreateWithFlags(&s1, cudaStreamNonBlocking);
        cudaStreamCreateWithFlags(&s2, cudaStreamNonBlocking);
        cudaEventCreateWithFlags(&evFork, cudaEventDisableTiming);
        cudaEventCreateWithFlags(&evWq, cudaEventDisableTiming);
        cudaEventCreateWithFlags(&evBA, cudaEventDisableTiming);
        cudaEventCreateWithFlags(&evZ, cudaEventDisableTiming);
        cudaFuncSetAttribute(h16gemm, cudaFuncAttributeMaxDynamicSharedMemorySize, GEMM_SMEM);
        cudaFuncSetAttribute(chunkA, cudaFuncAttributeMaxDynamicSharedMemorySize, SMA_BYTES);
        cudaFuncSetAttribute(chunkC, cudaFuncAttributeMaxDynamicSharedMemorySize, SMC_BYTES);
        cudaFuncSetAttribute(ba2_kernel, cudaFuncAttributeMaxDynamicSharedMemorySize, BA_SMEM);
    }

    // fork
    cudaEventRecord(evFork, 0);
    cudaStreamWaitEvent(s1, evFork, 0);
    cudaStreamWaitEvent(s2, evFork, 0);

    // s1: transpose W_qkvz
    transpose_half<<<dim3(QKVZ_N / 32, CC / 32), 256, 0, s1>>>(W_qkvz, wqt, CC, QKVZ_N);
    cudaEventRecord(evWq, s1);

    // s2: ba2 + transpose W_out
    ba2_kernel<<<BT / 64, 256, BA_SMEM, s2>>>(x, W_b, W_a, beta, alpha);
    transpose_half<<<dim3(CC / 32, CC / 32), 256, 0, s2>>>(W_out, wot, CC, CC);
    cudaEventRecord(evBA, s2);

    // main: to_half(x), GEMM1a (qkv columns, N=6144)
    to_half<<<(BT * CC / 8 + 255) / 256, 256>>>(x, xh, BT * CC / 8);
    cudaStreamWaitEvent(0, evWq, 0);
    h16gemm<<<dim3(CONV_DIM / 128, BT / 128), 128, GEMM_SMEM>>>(
        xh, wqt, qkvz, QKVZ_N, CC);
    cudaEventRecord(evFork, 0);   // "GEMM1a done"

    // s1: z-block GEMM concurrent with chunkA
    cudaStreamWaitEvent(s1, evFork, 0);
    h16gemm<<<dim3(VALUE_DIM / 128, BT / 128), 128, GEMM_SMEM, s1>>>(
        xh, wqt + (size_t)CONV_DIM * CC, qkvz + CONV_DIM, QKVZ_N, CC);
    cudaEventRecord(evZ, s1);

    // main: chunkA (conv fused) -> chunkB -> chunkC -> GEMM2
    cudaStreamWaitEvent(0, evBA, 0);
    chunkA<<<dim3(NCH, BH), 256, SMA_BYTES>>>(
        qkvz, conv_w, conv_state, input_pos, beta, alpha, attb, sinc, cbuf);
    chunkB<<<dim3(8, BH), 256>>>(sinc, spre, cbuf, rec_state, input_pos);
    cudaStreamWaitEvent(0, evZ, 0);
    chunkC<<<dim3(NCH, BH), 256, SMC_BYTES>>>(
        qkvz, conv_w, conv_state, input_pos, cbuf, spre, attb, norm_w, goh);
    h16gemm<<<dim3(CC / 128, BT / 128), 128, GEMM_SMEM>>>(
        goh, wot, out, CC, CC);
}